// round 4
// baseline (speedup 1.0000x reference)
#include <cuda_runtime.h>
#include <math.h>

// Problem constants
#define SEQ     2048
#define BATCH   16
#define DMODEL  512
#define FFDIM   2048
#define ROWS    (SEQ * BATCH)          // 32768
#define ALPHA_F 0.9f
#define EPS_F   1e-5f

// -------------------- scratch (no cudaMalloc allowed) --------------------
__device__ float g_Y [ (size_t)ROWS * DMODEL ];   // 64 MB  (LN outputs)
__device__ float g_Z [ (size_t)ROWS * DMODEL ];   // 64 MB  (projection z)
__device__ float g_X2[ (size_t)ROWS * DMODEL ];   // 64 MB  (x + attn)
__device__ float g_H [ (size_t)ROWS * FFDIM  ];   // 256 MB (relu hidden)

// -------------------- LayerNorm over D=512, one block per row --------------------
__global__ void __launch_bounds__(128) ln512_kernel(
    const float* __restrict__ X, const float* __restrict__ gamma,
    const float* __restrict__ beta, float* __restrict__ Y)
{
    __shared__ float ssum[4], ssq[4];
    const int row = blockIdx.x;
    const int tid = threadIdx.x;
    const float4* xr = reinterpret_cast<const float4*>(X + (size_t)row * DMODEL);
    float4 v = xr[tid];

    float s = v.x + v.y + v.z + v.w;
    float q = v.x*v.x + v.y*v.y + v.z*v.z + v.w*v.w;
    #pragma unroll
    for (int o = 16; o > 0; o >>= 1) {
        s += __shfl_down_sync(0xffffffffu, s, o);
        q += __shfl_down_sync(0xffffffffu, q, o);
    }
    const int wid = tid >> 5;
    if ((tid & 31) == 0) { ssum[wid] = s; ssq[wid] = q; }
    __syncthreads();
    const float ts = ssum[0] + ssum[1] + ssum[2] + ssum[3];
    const float tq = ssq[0]  + ssq[1]  + ssq[2]  + ssq[3];
    const float mean = ts * (1.0f / DMODEL);
    const float var  = tq * (1.0f / DMODEL) - mean * mean;
    const float r    = rsqrtf(var + EPS_F);

    const float4 gv = reinterpret_cast<const float4*>(gamma)[tid];
    const float4 bv = reinterpret_cast<const float4*>(beta)[tid];
    float4 o;
    o.x = (v.x - mean) * r * gv.x + bv.x;
    o.y = (v.y - mean) * r * gv.y + bv.y;
    o.z = (v.z - mean) * r * gv.z + bv.z;
    o.w = (v.w - mean) * r * gv.w + bv.w;
    reinterpret_cast<float4*>(Y + (size_t)row * DMODEL)[tid] = o;
}

// -------------------- causal exp-decay scan --------------------
// attn_i = S_i + c_i * z_i ; S_i = alpha*(S_{i-1}+z_i) ; c_i = 10*alpha^{i+2} - 8
// alpha^512 ~ 4e-24 -> chunked scan with 512-step lookback, zero carry-in.
#define SCAN_CHUNK    128
#define SCAN_LOOKBACK 512
__global__ void __launch_bounds__(128) scan_kernel(
    const float* __restrict__ Z, const float* __restrict__ X, float* __restrict__ X2)
{
    const int b     = blockIdx.y;
    const int cs    = blockIdx.x * SCAN_CHUNK;
    const int ce    = cs + SCAN_CHUNK;
    const int s0    = (cs - SCAN_LOOKBACK) > 0 ? (cs - SCAN_LOOKBACK) : 0;
    const int d4    = threadIdx.x * 4;

    float4 S = make_float4(0.f, 0.f, 0.f, 0.f);
    float  q = powf(ALPHA_F, (float)(s0 + 2));  // alpha^{s+2}

    for (int s = s0; s < ce; ++s) {
        const size_t off = ((size_t)s * BATCH + b) * DMODEL + d4;
        const float4 z = *reinterpret_cast<const float4*>(Z + off);
        S.x = ALPHA_F * (S.x + z.x);
        S.y = ALPHA_F * (S.y + z.y);
        S.z = ALPHA_F * (S.z + z.z);
        S.w = ALPHA_F * (S.w + z.w);
        if (s >= cs) {
            const float c = 10.0f * q - 8.0f;
            const float4 xv = *reinterpret_cast<const float4*>(X + off);
            float4 o;
            o.x = xv.x + S.x + c * z.x;
            o.y = xv.y + S.y + c * z.y;
            o.z = xv.z + S.z + c * z.z;
            o.w = xv.w + S.w + c * z.w;
            *reinterpret_cast<float4*>(X2 + off) = o;
        }
        q *= ALPHA_F;
    }
}

// -------------------- fp32 SIMT GEMM: C[M,N] = A[M,K] * B[N,K]^T (+bias, relu, residual) ------
// 128x128 tile, BK=8, 256 threads, 8x8 per thread (4+4 split strips for conflict-free LDS.128)
template<bool RELU, bool RES>
__global__ void __launch_bounds__(256) sgemm_nt(
    const float* __restrict__ A, const float* __restrict__ B,
    const float* __restrict__ bias, const float* __restrict__ res,
    float* __restrict__ C, int N, int K)
{
    __shared__ float As[8][128];
    __shared__ float Bs[8][128];

    const int tid = threadIdx.x;
    const int tx  = tid & 15;        // 0..15 -> n strips
    const int ty  = tid >> 4;        // 0..15 -> m strips
    const int m0  = blockIdx.y * 128;
    const int n0  = blockIdx.x * 128;

    const int lrow = tid >> 1;              // 0..127
    const int lk   = (tid & 1) * 4;         // 0 or 4
    const float* Aptr = A + (size_t)(m0 + lrow) * K + lk;
    const float* Bptr = B + (size_t)(n0 + lrow) * K + lk;

    float acc[8][8];
    #pragma unroll
    for (int i = 0; i < 8; i++)
        #pragma unroll
        for (int j = 0; j < 8; j++) acc[i][j] = 0.f;

    for (int k0 = 0; k0 < K; k0 += 8) {
        const float4 av = *reinterpret_cast<const float4*>(Aptr + k0);
        const float4 bv = *reinterpret_cast<const float4*>(Bptr + k0);
        As[lk+0][lrow] = av.x; As[lk+1][lrow] = av.y;
        As[lk+2][lrow] = av.z; As[lk+3][lrow] = av.w;
        Bs[lk+0][lrow] = bv.x; Bs[lk+1][lrow] = bv.y;
        Bs[lk+2][lrow] = bv.z; Bs[lk+3][lrow] = bv.w;
        __syncthreads();

        #pragma unroll
        for (int kk = 0; kk < 8; kk++) {
            float a[8], b[8];
            *reinterpret_cast<float4*>(&a[0]) = *reinterpret_cast<const float4*>(&As[kk][ty*4]);
            *reinterpret_cast<float4*>(&a[4]) = *reinterpret_cast<const float4*>(&As[kk][64 + ty*4]);
            *reinterpret_cast<float4*>(&b[0]) = *reinterpret_cast<const float4*>(&Bs[kk][tx*4]);
            *reinterpret_cast<float4*>(&b[4]) = *reinterpret_cast<const float4*>(&Bs[kk][64 + tx*4]);
            #pragma unroll
            for (int i = 0; i < 8; i++)
                #pragma unroll
                for (int j = 0; j < 8; j++)
                    acc[i][j] += a[i] * b[j];
        }
        __syncthreads();
    }

    // epilogue
    const float4 bias0 = *reinterpret_cast<const float4*>(bias + n0 + tx*4);
    const float4 bias1 = *reinterpret_cast<const float4*>(bias + n0 + 64 + tx*4);
    #pragma unroll
    for (int i = 0; i < 8; i++) {
        const int m = m0 + ty*4 + (i & 3) + (i >> 2) * 64;
        float4 c0, c1;
        c0.x = acc[i][0] + bias0.x; c0.y = acc[i][1] + bias0.y;
        c0.z = acc[i][2] + bias0.z; c0.w = acc[i][3] + bias0.w;
        c1.x = acc[i][4] + bias1.x; c1.y = acc[i][5] + bias1.y;
        c1.z = acc[i][6] + bias1.z; c1.w = acc[i][7] + bias1.w;
        if (RELU) {
            c0.x = fmaxf(c0.x, 0.f); c0.y = fmaxf(c0.y, 0.f);
            c0.z = fmaxf(c0.z, 0.f); c0.w = fmaxf(c0.w, 0.f);
            c1.x = fmaxf(c1.x, 0.f); c1.y = fmaxf(c1.y, 0.f);
            c1.z = fmaxf(c1.z, 0.f); c1.w = fmaxf(c1.w, 0.f);
        }
        const size_t off = (size_t)m * N + n0 + tx*4;
        if (RES) {
            const float4 r0 = *reinterpret_cast<const float4*>(res + off);
            const float4 r1 = *reinterpret_cast<const float4*>(res + off + 64);
            c0.x += r0.x; c0.y += r0.y; c0.z += r0.z; c0.w += r0.w;
            c1.x += r1.x; c1.y += r1.y; c1.z += r1.z; c1.w += r1.w;
        }
        *reinterpret_cast<float4*>(C + off)      = c0;
        *reinterpret_cast<float4*>(C + off + 64) = c1;
    }
}

// -------------------- host launch --------------------
extern "C" void kernel_launch(void* const* d_in, const int* in_sizes, int n_in,
                              void* d_out, int out_size)
{
    const float* x     = (const float*)d_in[0];
    const float* w_lin = (const float*)d_in[1];
    const float* b_lin = (const float*)d_in[2];
    const float* w1    = (const float*)d_in[3];
    const float* b1    = (const float*)d_in[4];
    const float* w2    = (const float*)d_in[5];
    const float* b2    = (const float*)d_in[6];
    const float* g1    = (const float*)d_in[7];
    const float* be1   = (const float*)d_in[8];
    const float* g2    = (const float*)d_in[9];
    const float* be2   = (const float*)d_in[10];
    float* out = (float*)d_out;

    float *Y, *Z, *X2, *H;
    cudaGetSymbolAddress((void**)&Y,  g_Y);
    cudaGetSymbolAddress((void**)&Z,  g_Z);
    cudaGetSymbolAddress((void**)&X2, g_X2);
    cudaGetSymbolAddress((void**)&H,  g_H);

    // 1) y1 = LN(x; g1, beta1)
    ln512_kernel<<<ROWS, 128>>>(x, g1, be1, Y);

    // 2) z = y1 @ w_lin^T + b_lin   (M=32768, N=512, K=512)
    sgemm_nt<false, false><<<dim3(DMODEL/128, ROWS/128), 256>>>(
        Y, w_lin, b_lin, nullptr, Z, DMODEL, DMODEL);

    // 3) x2 = x + W @ z  via linear recurrence scan
    scan_kernel<<<dim3(SEQ/SCAN_CHUNK, BATCH), 128>>>(Z, x, X2);

    // 4) y2 = LN(x2; g2, beta2)
    ln512_kernel<<<ROWS, 128>>>(X2, g2, be2, Y);

    // 5) h = relu(y2 @ w1^T + b1)   (M=32768, N=2048, K=512)
    sgemm_nt<true, false><<<dim3(FFDIM/128, ROWS/128), 256>>>(
        Y, w1, b1, nullptr, H, FFDIM, DMODEL);

    // 6) out = x2 + h @ w2^T + b2   (M=32768, N=512, K=2048)
    sgemm_nt<false, true><<<dim3(DMODEL/128, ROWS/128), 256>>>(
        H, w2, b2, X2, out, DMODEL, FFDIM);
}

// round 8
// speedup vs baseline: 2.8898x; 2.8898x over previous
#include <cuda_runtime.h>
#include <cstdint>
#include <math.h>

// Problem constants
#define SEQ     2048
#define BATCH   16
#define DMODEL  512
#define FFDIM   2048
#define ROWS    (SEQ * BATCH)          // 32768
#define ALPHA_F 0.9f
#define EPS_F   1e-5f

// -------------------- scratch (no cudaMalloc allowed) --------------------
__device__ float g_Y [ (size_t)ROWS * DMODEL ];   // 64 MB  (LN outputs)
__device__ float g_Z [ (size_t)ROWS * DMODEL ];   // 64 MB  (projection z)
__device__ float g_X2[ (size_t)ROWS * DMODEL ];   // 64 MB  (x + attn)
__device__ float g_H [ (size_t)ROWS * FFDIM  ];   // 256 MB (relu hidden)

// ==================== helpers (base sm_103 ISA only — no 'a' features) ====================
__device__ __forceinline__ uint32_t smem_u32(const void* p) {
    uint32_t a;
    asm("{ .reg .u64 t; cvta.to.shared.u64 t, %1; cvt.u32.u64 %0, t; }" : "=r"(a) : "l"(p));
    return a;
}
__device__ __forceinline__ void cp_async16(uint32_t dst, const void* src) {
    asm volatile("cp.async.cg.shared.global [%0], [%1], 16;" :: "r"(dst), "l"(src));
}
__device__ __forceinline__ void cp_commit() {
    asm volatile("cp.async.commit_group;" ::: "memory");
}
template<int N>
__device__ __forceinline__ void cp_wait() {
    asm volatile("cp.async.wait_group %0;" :: "n"(N) : "memory");
}
__device__ __forceinline__ uint32_t f2tf(float f) {
    uint32_t u;
    asm("cvt.rna.tf32.f32 %0, %1;" : "=r"(u) : "f"(f));
    return u;
}
__device__ __forceinline__ void mma_tf32(float* c, const uint32_t* a, const uint32_t* b) {
    asm volatile(
        "mma.sync.aligned.m16n8k8.row.col.f32.tf32.tf32.f32 "
        "{%0,%1,%2,%3}, {%4,%5,%6,%7}, {%8,%9}, {%0,%1,%2,%3};"
        : "+f"(c[0]), "+f"(c[1]), "+f"(c[2]), "+f"(c[3])
        : "r"(a[0]), "r"(a[1]), "r"(a[2]), "r"(a[3]), "r"(b[0]), "r"(b[1]));
}

// ==================== LayerNorm over D=512, one block per row ====================
__global__ void __launch_bounds__(128) ln512_kernel(
    const float* __restrict__ X, const float* __restrict__ gamma,
    const float* __restrict__ beta, float* __restrict__ Y)
{
    __shared__ float ssum[4], ssq[4];
    const int row = blockIdx.x;
    const int tid = threadIdx.x;
    const float4* xr = reinterpret_cast<const float4*>(X + (size_t)row * DMODEL);
    float4 v = xr[tid];

    float s = v.x + v.y + v.z + v.w;
    float q = v.x*v.x + v.y*v.y + v.z*v.z + v.w*v.w;
    #pragma unroll
    for (int o = 16; o > 0; o >>= 1) {
        s += __shfl_down_sync(0xffffffffu, s, o);
        q += __shfl_down_sync(0xffffffffu, q, o);
    }
    const int wid = tid >> 5;
    if ((tid & 31) == 0) { ssum[wid] = s; ssq[wid] = q; }
    __syncthreads();
    const float ts = ssum[0] + ssum[1] + ssum[2] + ssum[3];
    const float tq = ssq[0]  + ssq[1]  + ssq[2]  + ssq[3];
    const float mean = ts * (1.0f / DMODEL);
    const float var  = tq * (1.0f / DMODEL) - mean * mean;
    const float r    = rsqrtf(var + EPS_F);

    const float4 gv = reinterpret_cast<const float4*>(gamma)[tid];
    const float4 bv = reinterpret_cast<const float4*>(beta)[tid];
    float4 o;
    o.x = (v.x - mean) * r * gv.x + bv.x;
    o.y = (v.y - mean) * r * gv.y + bv.y;
    o.z = (v.z - mean) * r * gv.z + bv.z;
    o.w = (v.w - mean) * r * gv.w + bv.w;
    reinterpret_cast<float4*>(Y + (size_t)row * DMODEL)[tid] = o;
}

// ==================== causal exp-decay scan ====================
// attn_i = S_i + c_i*z_i ; S_i = alpha*(S_{i-1}+z_i) ; c_i = 10*alpha^{i+2} - 8
#define SCAN_CHUNK    128
#define SCAN_LOOKBACK 512
__global__ void __launch_bounds__(128) scan_kernel(
    const float* __restrict__ Z, const float* __restrict__ X, float* __restrict__ X2)
{
    const int b  = blockIdx.y;
    const int cs = blockIdx.x * SCAN_CHUNK;
    const int ce = cs + SCAN_CHUNK;
    const int s0 = (cs - SCAN_LOOKBACK) > 0 ? (cs - SCAN_LOOKBACK) : 0;
    const int d4 = threadIdx.x * 4;

    float4 S = make_float4(0.f, 0.f, 0.f, 0.f);
    float  q = powf(ALPHA_F, (float)(s0 + 2));

    for (int s = s0; s < ce; ++s) {
        const size_t off = ((size_t)s * BATCH + b) * DMODEL + d4;
        const float4 z = *reinterpret_cast<const float4*>(Z + off);
        S.x = ALPHA_F * (S.x + z.x);
        S.y = ALPHA_F * (S.y + z.y);
        S.z = ALPHA_F * (S.z + z.z);
        S.w = ALPHA_F * (S.w + z.w);
        if (s >= cs) {
            const float c = 10.0f * q - 8.0f;
            const float4 xv = *reinterpret_cast<const float4*>(X + off);
            float4 o;
            o.x = xv.x + S.x + c * z.x;
            o.y = xv.y + S.y + c * z.y;
            o.z = xv.z + S.z + c * z.z;
            o.w = xv.w + S.w + c * z.w;
            *reinterpret_cast<float4*>(X2 + off) = o;
        }
        q *= ALPHA_F;
    }
}

// ==================== tf32 mma.sync GEMM: C[M,N] = A[M,K] * B[N,K]^T ====================
// 128x128x32 CTA tile, 256 threads (8 warps, 2x4), warp tile 64x32 (4x4 m16n8k8 frags),
// 3-stage cp.async pipeline, XOR-swizzled SMEM (conflict-free fragment loads).
#define BM      128
#define BN      128
#define BK      32
#define STAGES  3
#define STAGE_BYTES 32768                 // A 16KB + B 16KB
#define GSM_BYTES   (STAGES * STAGE_BYTES) // 98304

// swizzled float index within a [128][32] tile: row*32 + (col ^ ((row&7)<<2))
__device__ __forceinline__ int swz(int row, int col) {
    return row * 32 + (col ^ ((row & 7) << 2));
}

__device__ __forceinline__ void load_stage(
    const float* __restrict__ A, const float* __restrict__ B,
    int K, int m0, int n0, int k0,
    uint32_t sA_u, uint32_t sB_u, int tid)
{
    #pragma unroll
    for (int i = 0; i < 4; i++) {
        const int slot = i * 256 + tid;
        const int row  = slot >> 3;          // 0..127
        const int c4   = slot & 7;           // 16B chunk within 128B row
        const uint32_t sw = (uint32_t)(row * 128 + ((c4 * 16) ^ ((row & 7) << 4)));
        cp_async16(sA_u + sw, A + (size_t)(m0 + row) * K + k0 + c4 * 4);
        cp_async16(sB_u + sw, B + (size_t)(n0 + row) * K + k0 + c4 * 4);
    }
}

template<bool RELU, bool RES>
__global__ void __launch_bounds__(256) mm_tf32_nt(
    const float* __restrict__ A, const float* __restrict__ B,
    const float* __restrict__ bias, const float* __restrict__ res,
    float* __restrict__ C, int N, int K)
{
    extern __shared__ char smem[];
    const uint32_t sbase = smem_u32(smem);
    const int tid  = threadIdx.x;
    const int wrp  = tid >> 5;
    const int lane = tid & 31;
    const int q    = lane >> 2;        // group id 0..7
    const int r    = lane & 3;         // thread in group
    const int wm   = wrp >> 2;         // 0..1 (m)
    const int wn   = wrp & 3;          // 0..3 (n)
    const int m0   = blockIdx.y * BM;
    const int n0   = blockIdx.x * BN;
    const int NC   = K / BK;

    float acc[4][4][4];
    #pragma unroll
    for (int mi = 0; mi < 4; mi++)
        #pragma unroll
        for (int ni = 0; ni < 4; ni++)
            #pragma unroll
            for (int e = 0; e < 4; e++) acc[mi][ni][e] = 0.f;

    // prologue: first STAGES-1 chunks
    #pragma unroll
    for (int s = 0; s < STAGES - 1; ++s) {
        load_stage(A, B, K, m0, n0, s * BK,
                   sbase + s * STAGE_BYTES, sbase + s * STAGE_BYTES + 16384, tid);
        cp_commit();
    }

    for (int c = 0; c < NC; ++c) {
        cp_wait<STAGES - 2>();
        __syncthreads();

        const int pf = c + STAGES - 1;
        if (pf < NC) {
            const int ps = pf % STAGES;
            load_stage(A, B, K, m0, n0, pf * BK,
                       sbase + ps * STAGE_BYTES, sbase + ps * STAGE_BYTES + 16384, tid);
        }
        cp_commit();

        const int cs = c % STAGES;
        const float* sA = reinterpret_cast<const float*>(smem + cs * STAGE_BYTES);
        const float* sB = reinterpret_cast<const float*>(smem + cs * STAGE_BYTES + 16384);

        #pragma unroll
        for (int ks = 0; ks < 4; ++ks) {
            const int kb = ks * 8;
            uint32_t afr[4][4];
            #pragma unroll
            for (int mi = 0; mi < 4; mi++) {
                const int row = wm * 64 + mi * 16 + q;   // row&7 == q
                afr[mi][0] = f2tf(sA[swz(row,     kb + r)]);
                afr[mi][1] = f2tf(sA[swz(row + 8, kb + r)]);
                afr[mi][2] = f2tf(sA[swz(row,     kb + r + 4)]);
                afr[mi][3] = f2tf(sA[swz(row + 8, kb + r + 4)]);
            }
            uint32_t bfr[4][2];
            #pragma unroll
            for (int ni = 0; ni < 4; ni++) {
                const int nrow = wn * 32 + ni * 8 + q;   // nrow&7 == q
                bfr[ni][0] = f2tf(sB[swz(nrow, kb + r)]);
                bfr[ni][1] = f2tf(sB[swz(nrow, kb + r + 4)]);
            }
            #pragma unroll
            for (int mi = 0; mi < 4; mi++)
                #pragma unroll
                for (int ni = 0; ni < 4; ni++)
                    mma_tf32(acc[mi][ni], afr[mi], bfr[ni]);
        }
    }
    cp_wait<0>();

    // epilogue: bias (+relu) (+residual), float2 stores
    const int m_base = m0 + wm * 64;
    const int n_base = n0 + wn * 32;
    #pragma unroll
    for (int mi = 0; mi < 4; mi++) {
        const int row = m_base + mi * 16 + q;
        #pragma unroll
        for (int ni = 0; ni < 4; ni++) {
            const int col = n_base + ni * 8 + r * 2;
            const float b0 = bias[col], b1 = bias[col + 1];
            float2 v0, v1;
            v0.x = acc[mi][ni][0] + b0; v0.y = acc[mi][ni][1] + b1;
            v1.x = acc[mi][ni][2] + b0; v1.y = acc[mi][ni][3] + b1;
            if (RELU) {
                v0.x = fmaxf(v0.x, 0.f); v0.y = fmaxf(v0.y, 0.f);
                v1.x = fmaxf(v1.x, 0.f); v1.y = fmaxf(v1.y, 0.f);
            }
            const size_t off0 = (size_t)row * N + col;
            const size_t off1 = (size_t)(row + 8) * N + col;
            if (RES) {
                const float2 r0 = *reinterpret_cast<const float2*>(res + off0);
                const float2 r1 = *reinterpret_cast<const float2*>(res + off1);
                v0.x += r0.x; v0.y += r0.y;
                v1.x += r1.x; v1.y += r1.y;
            }
            *reinterpret_cast<float2*>(C + off0) = v0;
            *reinterpret_cast<float2*>(C + off1) = v1;
        }
    }
}

// ==================== host launch ====================
extern "C" void kernel_launch(void* const* d_in, const int* in_sizes, int n_in,
                              void* d_out, int out_size)
{
    const float* x     = (const float*)d_in[0];
    const float* w_lin = (const float*)d_in[1];
    const float* b_lin = (const float*)d_in[2];
    const float* w1    = (const float*)d_in[3];
    const float* b1    = (const float*)d_in[4];
    const float* w2    = (const float*)d_in[5];
    const float* b2    = (const float*)d_in[6];
    const float* g1    = (const float*)d_in[7];
    const float* be1   = (const float*)d_in[8];
    const float* g2    = (const float*)d_in[9];
    const float* be2   = (const float*)d_in[10];
    float* out = (float*)d_out;

    float *Y, *Z, *X2, *H;
    cudaGetSymbolAddress((void**)&Y,  g_Y);
    cudaGetSymbolAddress((void**)&Z,  g_Z);
    cudaGetSymbolAddress((void**)&X2, g_X2);
    cudaGetSymbolAddress((void**)&H,  g_H);

    cudaFuncSetAttribute(mm_tf32_nt<false, false>,
                         cudaFuncAttributeMaxDynamicSharedMemorySize, GSM_BYTES);
    cudaFuncSetAttribute(mm_tf32_nt<true,  false>,
                         cudaFuncAttributeMaxDynamicSharedMemorySize, GSM_BYTES);
    cudaFuncSetAttribute(mm_tf32_nt<false, true>,
                         cudaFuncAttributeMaxDynamicSharedMemorySize, GSM_BYTES);

    // 1) y1 = LN(x; g1, beta1)
    ln512_kernel<<<ROWS, 128>>>(x, g1, be1, Y);

    // 2) z = y1 @ w_lin^T + b_lin   (M=32768, N=512, K=512)
    mm_tf32_nt<false, false><<<dim3(DMODEL/BN, ROWS/BM), 256, GSM_BYTES>>>(
        Y, w_lin, b_lin, nullptr, Z, DMODEL, DMODEL);

    // 3) x2 = x + W @ z  via linear recurrence scan
    scan_kernel<<<dim3(SEQ/SCAN_CHUNK, BATCH), 128>>>(Z, x, X2);

    // 4) y2 = LN(x2; g2, beta2)
    ln512_kernel<<<ROWS, 128>>>(X2, g2, be2, Y);

    // 5) h = relu(y2 @ w1^T + b1)   (M=32768, N=2048, K=512)
    mm_tf32_nt<true, false><<<dim3(FFDIM/BN, ROWS/BM), 256, GSM_BYTES>>>(
        Y, w1, b1, nullptr, H, FFDIM, DMODEL);

    // 6) out = x2 + h @ w2^T + b2   (M=32768, N=512, K=2048)
    mm_tf32_nt<false, true><<<dim3(DMODEL/BN, ROWS/BM), 256, GSM_BYTES>>>(
        H, w2, b2, X2, out, DMODEL, FFDIM);
}